// round 5
// baseline (speedup 1.0000x reference)
#include <cuda_runtime.h>
#include <cstdint>
#include <cstddef>

#define NS   730
#define NG   1000
#define MUc  8
#define NCH  (NG*MUc)
#define BATCH 8
#define PRECSf 1e-05f

__constant__ float LBc[13] = {1.0f, 50.0f, 0.05f, 0.01f, 0.001f, 0.2f, 0.0f, 0.0f, -2.5f, 0.5f, 0.0f, 0.0f, 0.3f};
__constant__ float UBc[13] = {6.0f, 1000.0f, 0.9f, 0.5f, 0.2f, 1.0f, 10.0f, 100.0f, 2.5f, 10.0f, 0.1f, 0.2f, 5.0f};

__device__ __forceinline__ float fast_lg2(float a) {
    float r; asm("lg2.approx.f32 %0, %1;" : "=f"(r) : "f"(a)); return r;
}
__device__ __forceinline__ float fast_ex2(float a) {
    float r; asm("ex2.approx.f32 %0, %1;" : "=f"(r) : "f"(a)); return r;
}

// ============================================================================
// Specialized path: time-varying slots are exactly {12=BETAET, 0=BETA}.
// ============================================================================
__device__ __forceinline__ void run_spec(
    const float* __restrict__ x, const float* __restrict__ par,
    float* __restrict__ out, int g, int m, int staind,
    const float* __restrict__ ppBET, const float* __restrict__ ppB)
{
    // ---- chain-constant parameters from the staind row ----
    float cp[13];
    {
        const float* pb = par + ((size_t)staind*NG + (size_t)g)*13u*MUc + m;
        #pragma unroll
        for (int p = 0; p < 13; p++)
            cp[p] = fmaf(pb[(size_t)p*MUc], (UBc[p]-LBc[p]), LBc[p]);
    }
    const float FC=cp[1], K0=cp[2], K1=cp[3], K2=cp[4], LP=cp[5],
                PERCc=cp[6], UZL=cp[7], TT=cp[8], CFMAX=cp[9], CFR=cp[10], CWH=cp[11];
    // derived chain-invariants
    const float lgFC      = fast_lg2(FC);
    const float lgLPFC    = fast_lg2(LP*FC);
    const float negCFMAXTT= -CFMAX*TT;     // m0 = CFMAX*T + negCFMAXTT = CFMAX*(T-TT)
    const float negCFR    = -CFR;          // r0 = negCFR*m0 = CFR*CFMAX*(TT-T)
    const float dBET = UBc[12]-LBc[12], lbBET = LBc[12];
    const float dB   = UBc[0] -LBc[0],  lbB   = LBc[0];

    const float* xp = x + (size_t)g*3;
    const long XS = (long)NG*3;
    const long PS = (long)NG*13*MUc;

    float SP=0.001f, MW=0.001f, SM=0.001f, SUZ=0.001f, SLZ=0.001f;
    const float invmu = 1.0f/(float)MUc;
    const unsigned FULL = 0xffffffffu;
    const bool hi4 = (m & 4) != 0, hi2 = (m & 2) != 0, hi1 = (m & 1) != 0;
    float* outp = out + (size_t)m*NG + g;   // step s=b*8+m -> outp + b*8000

    // raw load buffers (current batch)
    float cP[BATCH], cT[BATCH], cE[BATCH], cBT[BATCH], cB[BATCH];
    #pragma unroll
    for (int j = 0; j < BATCH; j++) {
        cP [j] = xp[(long)j*XS + 0];
        cT [j] = xp[(long)j*XS + 1];
        cE [j] = xp[(long)j*XS + 2];
        cBT[j] = ppBET[(long)j*PS];
        cB [j] = ppB  [(long)j*PS];
    }

    auto step = [&](float rain, float snow, float m0, float r0,
                    float BETA, float C1, float BETAET, float C2, float E_) -> float {
        // snow module (off critical chain)
        SP += snow;
        float melt = fminf(fmaxf(m0, 0.0f), SP);
        MW += melt; SP -= melt;
        float refr = fminf(fmaxf(r0, 0.0f), MW);
        SP += refr; MW -= refr;
        float tosoil = fmaxf(fmaf(-CWH, SP, MW), 0.0f);
        MW -= tosoil;
        float rt = rain + tosoil;
        // soil module — the loop-carried critical chain
        float lgSM = fast_lg2(SM);
        float sw   = fast_ex2(fminf(fmaf(BETA, lgSM, C1), 0.0f));   // clip((SM/FC)^BETA,0,1)
        float recharge = rt * sw;
        float smrt = SM + rt;                   // parallel to lg2/ex2
        float SM1  = smrt - recharge;
        float SM2  = fminf(SM1, FC);
        float excess = SM1 - SM2;               // off-chain
        float lgSM2 = fast_lg2(SM2);
        float ea    = fast_ex2(fmaf(BETAET, lgSM2, C2));  // = E * (SM2/(LP*FC))^BETAET
        float ETact = fminf(fminf(SM2, E_), ea);          // min(SM2, E*clip(ef,0,1))
        SM = fmaxf(SM2 - ETact, PRECSf);
        // routing (off-chain)
        SUZ += recharge + excess;
        float PERC = fminf(SUZ, PERCc);
        SUZ -= PERC;
        float Q0 = K0 * fmaxf(SUZ - UZL, 0.0f);
        SUZ -= Q0;
        float Q1 = K1 * SUZ;
        SUZ -= Q1;
        SLZ += PERC;
        float Q2 = K2 * SLZ;
        SLZ -= Q2;
        return Q0 + Q1 + Q2;
    };

    auto do_batch = [&](int b, const float* P, const float* T, const float* E,
                        const float* BTraw, const float* Braw) {
        // off-chain per-batch precompute (fills load/MUFU shadows)
        float rain[BATCH], snow[BATCH], m0[BATCH], r0[BATCH],
              BET[BATCH], BB[BATCH], C1[BATCH], C2[BATCH];
        #pragma unroll
        for (int j = 0; j < BATCH; j++) {
            float BETAET = fmaf(BTraw[j], dBET, lbBET);
            float BETA   = fmaf(Braw[j],  dB,   lbB);
            m0[j]  = fmaf(CFMAX, T[j], negCFMAXTT);     // CFMAX*(T-TT)
            r0[j]  = negCFR * m0[j];                    // CFR*CFMAX*(TT-T)
            rain[j]= (T[j] >= TT) ? P[j] : 0.0f;        // exact reference condition
            snow[j]= P[j] - rain[j];
            C1[j]  = -BETA * lgFC;
            C2[j]  = fmaf(-BETAET, lgLPFC, fast_lg2(E[j]));
            BET[j] = BETAET; BB[j] = BETA;
        }
        float q[BATCH];
        #pragma unroll
        for (int j = 0; j < BATCH; j++)
            q[j] = step(rain[j], snow[j], m0[j], r0[j], BB[j], C1[j], BET[j], C2[j], E[j]);
        // recursive-halving reduce-scatter: lane m owns total of step b*8+m
        float s1[4];
        #pragma unroll
        for (int e = 0; e < 4; e++) {
            float send = hi4 ? q[e] : q[e+4];
            float recv = __shfl_xor_sync(FULL, send, 4);
            s1[e] = (hi4 ? q[e+4] : q[e]) + recv;
        }
        float s2[2];
        #pragma unroll
        for (int e = 0; e < 2; e++) {
            float send = hi2 ? s1[e] : s1[e+2];
            float recv = __shfl_xor_sync(FULL, send, 2);
            s2[e] = (hi2 ? s1[e+2] : s1[e]) + recv;
        }
        float send = hi1 ? s2[0] : s2[1];
        float recv = __shfl_xor_sync(FULL, send, 1);
        float tot  = (hi1 ? s2[1] : s2[0]) + recv;
        outp[(size_t)b*(BATCH*NG)] = tot * invmu;
    };

    // main loop: 91 full batches (b = 0..90, steps 0..727).
    // Prefetch of batch b+1 happens for b < 90 only (all accesses in-bounds).
    for (int b = 0; b <= 90; b++) {
        float nP[BATCH], nT[BATCH], nE[BATCH], nBT[BATCH], nB[BATCH];
        const bool pf = (b < 90);
        if (pf) {
            long tn = (long)(b+1)*BATCH;
            const float* xq = xp + tn*XS;
            const float* qT = ppBET + tn*PS;
            const float* qB = ppB + tn*PS;
            #pragma unroll
            for (int j = 0; j < BATCH; j++) {
                nP [j] = xq[(long)j*XS + 0];
                nT [j] = xq[(long)j*XS + 1];
                nE [j] = xq[(long)j*XS + 2];
                nBT[j] = qT[(long)j*PS];
                nB [j] = qB[(long)j*PS];
            }
        }
        do_batch(b, cP, cT, cE, cBT, cB);
        if (pf) {
            #pragma unroll
            for (int j = 0; j < BATCH; j++) {
                cP[j]=nP[j]; cT[j]=nT[j]; cE[j]=nE[j]; cBT[j]=nBT[j]; cB[j]=nB[j];
            }
        }
    }
    // tail: steps 728, 729
    #pragma unroll
    for (int t = 91*BATCH; t < NS; t++) {
        float P_ = xp[(long)t*XS + 0];
        float T_ = xp[(long)t*XS + 1];
        float E_ = xp[(long)t*XS + 2];
        float BETAET = fmaf(ppBET[(long)t*PS], dBET, lbBET);
        float BETA   = fmaf(ppB  [(long)t*PS], dB,   lbB);
        float m0 = fmaf(CFMAX, T_, negCFMAXTT);
        float r0 = negCFR * m0;
        float rain = (T_ >= TT) ? P_ : 0.0f;
        float snow = P_ - rain;
        float C1 = -BETA * lgFC;
        float C2 = fmaf(-BETAET, lgLPFC, fast_lg2(E_));
        float qv = step(rain, snow, m0, r0, BETA, C1, BETAET, C2, E_);
        qv += __shfl_xor_sync(FULL, qv, 1);
        qv += __shfl_xor_sync(FULL, qv, 2);
        qv += __shfl_xor_sync(FULL, qv, 4);
        if (m == 0) out[(size_t)t*NG + g] = qv * invmu;
    }
}

// ============================================================================
// Generic fallback (any i0/i1): straightforward per-step evaluation.
// ============================================================================
__device__ __forceinline__ void run_generic(
    const float* __restrict__ x, const float* __restrict__ par,
    float* __restrict__ out, int g, int m, int staind, int i0, int i1)
{
    float cp[13];
    {
        const float* pb = par + ((size_t)staind*NG + (size_t)g)*13u*MUc + m;
        #pragma unroll
        for (int p = 0; p < 13; p++)
            cp[p] = fmaf(pb[(size_t)p*MUc], (UBc[p]-LBc[p]), LBc[p]);
    }
    const float lb0 = LBc[i0], d0 = UBc[i0]-LBc[i0];
    const float lb1 = LBc[i1], d1 = UBc[i1]-LBc[i1];
    const float* xp  = x   + (size_t)g*3;
    const float* pp0 = par + ((size_t)g*13 + (size_t)i0)*MUc + m;
    const float* pp1 = par + ((size_t)g*13 + (size_t)i1)*MUc + m;
    const long XS = (long)NG*3, PS = (long)NG*13*MUc;

    float SP=0.001f, MW=0.001f, SM=0.001f, SUZ=0.001f, SLZ=0.001f;
    const float invmu = 1.0f/(float)MUc;
    const unsigned FULL = 0xffffffffu;

    for (int t = 0; t < NS; t++) {
        float P_ = xp[(long)t*XS + 0];
        float T_ = xp[(long)t*XS + 1];
        float E_ = xp[(long)t*XS + 2];
        float v0 = fmaf(pp0[(long)t*PS], d0, lb0);
        float v1 = fmaf(pp1[(long)t*PS], d1, lb1);
        float pr[13];
        #pragma unroll
        for (int p = 0; p < 13; p++) {
            float v = cp[p];
            if (p == i0) v = v0;
            if (p == i1) v = v1;
            pr[p] = v;
        }
        float BETA=pr[0], FC=pr[1], K0=pr[2], K1=pr[3], K2=pr[4], LP=pr[5],
              PERCc=pr[6], UZL=pr[7], TT=pr[8], CFMAX=pr[9], CFR=pr[10],
              CWH=pr[11], BETAET=pr[12];
        float rain = (T_ >= TT) ? P_ : 0.0f;
        float snow = P_ - rain;
        SP += snow;
        float melt = fminf(fmaxf(CFMAX*(T_-TT), 0.0f), SP);
        MW += melt; SP -= melt;
        float refr = fminf(fmaxf(CFR*CFMAX*(TT-T_), 0.0f), MW);
        SP += refr; MW -= refr;
        float tosoil = fmaxf(MW - CWH*SP, 0.0f);
        MW -= tosoil;
        float sw = fminf(fast_ex2(BETA*(fast_lg2(SM) - fast_lg2(FC))), 1.0f);
        float rt = rain + tosoil;
        float recharge = rt * sw;
        float SM1 = SM + rt - recharge;
        float excess = fmaxf(SM1 - FC, 0.0f);
        float SM2 = SM1 - excess;
        float ef = fminf(fast_ex2(BETAET*(fast_lg2(SM2) - fast_lg2(LP*FC))), 1.0f);
        float ETact = fminf(SM2, E_*ef);
        SM = fmaxf(SM2 - ETact, PRECSf);
        SUZ += recharge + excess;
        float PERC = fminf(SUZ, PERCc);
        SUZ -= PERC;
        float Q0 = K0 * fmaxf(SUZ - UZL, 0.0f);
        SUZ -= Q0;
        float Q1 = K1 * SUZ;
        SUZ -= Q1;
        SLZ += PERC;
        float Q2 = K2 * SLZ;
        SLZ -= Q2;
        float qv = Q0 + Q1 + Q2;
        qv += __shfl_xor_sync(FULL, qv, 1);
        qv += __shfl_xor_sync(FULL, qv, 2);
        qv += __shfl_xor_sync(FULL, qv, 4);
        if (m == 0) out[(size_t)t*NG + g] = qv * invmu;
    }
}

__global__ void __launch_bounds__(64, 1)
hbv_kernel(const float* __restrict__ x, const float* __restrict__ par,
           const int* __restrict__ staind_p, const int* __restrict__ tdlst_p,
           int n_td, float* __restrict__ out)
{
    int tid = blockIdx.x * 64 + threadIdx.x;   // 8000 threads exactly
    int g = tid >> 3;
    int m = tid & 7;
    int staind = staind_p[0];
    int t0 = tdlst_p[0];
    int t1 = (n_td > 1) ? tdlst_p[1] : t0;
    int i0 = ((t0 - 1) % 13 + 13) % 13;
    int i1 = ((t1 - 1) % 13 + 13) % 13;

    const long PS_base = (size_t)g*13*MUc + m;
    if ((i0 == 12 && i1 == 0) || (i0 == 0 && i1 == 12)) {
        run_spec(x, par, out, g, m, staind,
                 par + PS_base + 12*MUc, par + PS_base + 0*MUc);
    } else {
        run_generic(x, par, out, g, m, staind, i0, i1);
    }
}

extern "C" void kernel_launch(void* const* d_in, const int* in_sizes, int n_in,
                              void* d_out, int out_size)
{
    const float* x      = (const float*)d_in[0];   // (730, 1000, 3) f32
    const float* par    = (const float*)d_in[1];   // (730, 1000, 13, 8) f32
    const int*   staind = (const int*)d_in[2];     // scalar
    const int*   tdlst  = (const int*)d_in[3];     // (2,) int32
    int n_td = in_sizes[3];
    (void)n_in; (void)out_size;
    hbv_kernel<<<NCH/64, 64>>>(x, par, staind, tdlst, n_td, (float*)d_out);
}